// round 9
// baseline (speedup 1.0000x reference)
#include <cuda_runtime.h>
#include <math.h>
#include <stdint.h>

#define B_  128
#define T_  1024
#define NX_ 256
#define NH_ 512
#define NY_ 256

// Per-CTA progress flags: g_flag[bt][jt], padded row to 32 words.
__device__ unsigned g_flag[16][32];

// ---------------------------------------------------------------------------
// Generic NT SGEMM (proven): C[m][n] = sum_k A[m][k] * B[n][k]
// ---------------------------------------------------------------------------
template <int BM, int BN, int BK, int TM, int TN, int NT>
__global__ __launch_bounds__(NT) void sgemm_nt(
    const float* __restrict__ A,
    const float* __restrict__ Bm,
    float* __restrict__ C,
    int M, int N, int K)
{
    __shared__ float As[BK][BM];
    __shared__ float Bs[BK][BN];

    const int tid = threadIdx.x;
    const int m0 = blockIdx.y * BM;
    const int n0 = blockIdx.x * BN;
    const int tx = tid % (BN / TN);
    const int ty = tid / (BN / TN);

    float acc[TM][TN];
#pragma unroll
    for (int i = 0; i < TM; i++)
#pragma unroll
        for (int j = 0; j < TN; j++) acc[i][j] = 0.0f;

    for (int k0 = 0; k0 < K; k0 += BK) {
#pragma unroll
        for (int i = tid; i < BM * (BK / 4); i += NT) {
            int m = i / (BK / 4);
            int kq = (i % (BK / 4)) * 4;
            float4 v = *(const float4*)(A + (long)(m0 + m) * K + k0 + kq);
            As[kq + 0][m] = v.x;
            As[kq + 1][m] = v.y;
            As[kq + 2][m] = v.z;
            As[kq + 3][m] = v.w;
        }
#pragma unroll
        for (int i = tid; i < BN * (BK / 4); i += NT) {
            int n = i / (BK / 4);
            int kq = (i % (BK / 4)) * 4;
            float4 v = *(const float4*)(Bm + (long)(n0 + n) * K + k0 + kq);
            Bs[kq + 0][n] = v.x;
            Bs[kq + 1][n] = v.y;
            Bs[kq + 2][n] = v.z;
            Bs[kq + 3][n] = v.w;
        }
        __syncthreads();

#pragma unroll
        for (int k = 0; k < BK; ++k) {
            float a[TM], b[TN];
#pragma unroll
            for (int i = 0; i < TM; i++) a[i] = As[k][ty * TM + i];
#pragma unroll
            for (int j = 0; j < TN; j++) b[j] = Bs[k][tx * TN + j];
#pragma unroll
            for (int i = 0; i < TM; i++)
#pragma unroll
                for (int j = 0; j < TN; j++) acc[i][j] = fmaf(a[i], b[j], acc[i][j]);
        }
        __syncthreads();
    }

#pragma unroll
    for (int i = 0; i < TM; i++) {
        float4 v = make_float4(acc[i][0], acc[i][1], acc[i][2], acc[i][3]);
        *(float4*)(C + (long)(m0 + ty * TM + i) * N + n0 + tx * TN) = v;
    }
}

// ---------------------------------------------------------------------------
// Helpers
// ---------------------------------------------------------------------------
__device__ __forceinline__ void ffma2(unsigned long long& d,
                                      unsigned long long a, unsigned long long b)
{
    asm("fma.rn.f32x2 %0, %1, %2, %0;" : "+l"(d) : "l"(a), "l"(b));
}
__device__ __forceinline__ void unpack2(unsigned long long v, float& lo, float& hi)
{
    asm("mov.b64 {%0, %1}, %2;" : "=f"(lo), "=f"(hi) : "l"(v));
}
__device__ __forceinline__ unsigned ld_acq(const unsigned* p)
{
    unsigned v;
    asm volatile("ld.global.acquire.gpu.u32 %0, [%1];" : "=r"(v) : "l"(p) : "memory");
    return v;
}
__device__ __forceinline__ void st_rel(unsigned* p, unsigned v)
{
    asm volatile("st.global.release.gpu.u32 [%0], %1;" :: "l"(p), "r"(v) : "memory");
}

// ---------------------------------------------------------------------------
// Sequential recurrence v4.
// Grid = 128 CTAs = 16 bt x 8 jt. 256 threads = 8 warps, k-split 64 each.
// CTA owns 8 batches x 64 output columns. Per thread: 2 columns (lane*2+c),
// Wh slice in 64 u64 registers (128 regs), resident for all steps.
// Warp-local h reload (2KB/warp, private SMEM, no pre-kloop barrier).
// Cross-CTA sync: per-CTA release flags + per-warp acquire polls with
// tolerance (v - t) <= 1 (skew provably bounded by 1).
// SMEM: hT[8 warps][8 b][68] f32 (17.4KB) + red[8][8][64] u64 (32KB).
// ---------------------------------------------------------------------------
#define NTHR     256
#define HT_WSTR  (8 * 68)             // floats per warp region
#define RED_OFF  (8 * HT_WSTR)        // float index where red starts (4352)
#define SMEM_BYTES (RED_OFF * 4 + 8 * 8 * 64 * 8)   // 17408 + 32768 = 50176

__global__ __launch_bounds__(NTHR, 1) void rnn_seq4(
    const float* __restrict__ Wh,   // [NH][NH]
    const float* __restrict__ h0,   // [B][NH]
    float* __restrict__ hs)         // [B][T][NH]: pre in, h out (in place)
{
    extern __shared__ float sm[];
    unsigned long long* red = (unsigned long long*)(sm + RED_OFF);  // [w][b][j]

    const int tid  = threadIdx.x;
    const int wid  = tid >> 5;
    const int lane = tid & 31;

    const int jt  = blockIdx.x & 7;
    const int bt  = blockIdx.x >> 3;
    const int j0g = jt * 64;
    const int b0  = bt * 8;
    const int kw0 = wid * 64;

    float* hTw = sm + wid * HT_WSTR;     // this warp's private [8][68]

    // ---- Wh slice into registers: W[c*32 + 2q{,+1}] for cols lane*2+c ----
    unsigned long long W[64];
#pragma unroll
    for (int c = 0; c < 2; ++c) {
        const float* row = Wh + (size_t)(j0g + lane * 2 + c) * NH_ + kw0;
#pragma unroll
        for (int q = 0; q < 16; ++q) {
            ulonglong2 v = *(const ulonglong2*)(row + q * 4);
            W[c * 32 + 2 * q]     = v.x;
            W[c * 32 + 2 * q + 1] = v.y;
        }
    }

    // reload mapping: lane -> (batch rb, 16-float segment seg)
    const int rb  = lane >> 2;
    const int seg = lane & 3;

    // epilogue mapping: outputs out0=tid, out1=tid+256; b=out>>6, j=out&63
    const int eb0 = tid >> 6;            // 0..3
    const int eb1 = eb0 + 4;             // 4..7
    const int ej  = tid & 63;

    unsigned* flags = &g_flag[bt][0];

    for (int t = 0; t < T_; ++t) {
        // ---- prefetch this step's pre-activations ----
        float pre0 = __ldcg(hs + ((size_t)(b0 + eb0) * T_ + t) * NH_ + j0g + ej);
        float pre1 = __ldcg(hs + ((size_t)(b0 + eb1) * T_ + t) * NH_ + j0g + ej);

        // ---- per-warp domain wait: all 8 CTAs published h_{t-1} ----
        if (t > 0) {
            for (;;) {
                unsigned v = (lane < 8) ? ld_acq(flags + lane) : (unsigned)t;
                if (__all_sync(0xffffffffu, (v - (unsigned)t) <= 1u)) break;
                __nanosleep(20);
            }
        }

        // ---- warp-local reload: h[rb][kw0 + seg*16 .. +16) -> hTw ----
        {
            const float* src = (t == 0)
                ? h0 + (size_t)(b0 + rb) * NH_ + kw0 + seg * 16
                : hs + ((size_t)(b0 + rb) * T_ + (t - 1)) * NH_ + kw0 + seg * 16;
#pragma unroll
            for (int q = 0; q < 4; ++q) {
                float4 v = __ldcg((const float4*)(src + q * 4));
                *(float4*)&hTw[rb * 68 + seg * 16 + q * 4] = v;
            }
        }
        // no barrier: hTw is produced and consumed by this warp only.

        // ---- k-loop: 4 FFMA2 per broadcast LDS.128 ----
        unsigned long long acc[8][2];
#pragma unroll
        for (int b = 0; b < 8; ++b) { acc[b][0] = 0ull; acc[b][1] = 0ull; }

#pragma unroll
        for (int b = 0; b < 8; ++b) {
            const float* hb = &hTw[b * 68];
#pragma unroll
            for (int q = 0; q < 16; ++q) {
                ulonglong2 va = *(const ulonglong2*)(hb + q * 4);   // broadcast
                ffma2(acc[b][0], va.x, W[2 * q]);
                ffma2(acc[b][0], va.y, W[2 * q + 1]);
                ffma2(acc[b][1], va.x, W[32 + 2 * q]);
                ffma2(acc[b][1], va.y, W[32 + 2 * q + 1]);
            }
        }

        // ---- stash partials: red[wid][b][lane*2 + c] as one STS.128 ----
#pragma unroll
        for (int b = 0; b < 8; ++b) {
            ulonglong2 v; v.x = acc[b][0]; v.y = acc[b][1];
            *(ulonglong2*)&red[(size_t)wid * 512 + b * 64 + lane * 2] = v;
        }
        __syncthreads();

        // ---- reduce 8 warps, fold k-pairs, add pre, tanh, publish ----
        {
            float s0 = pre0, s1 = pre1;
#pragma unroll
            for (int w = 0; w < 8; ++w) {
                float lo, hi;
                unpack2(red[(size_t)w * 512 + eb0 * 64 + ej], lo, hi);
                s0 += lo + hi;
                unpack2(red[(size_t)w * 512 + eb1 * 64 + ej], lo, hi);
                s1 += lo + hi;
            }
            float hv0 = tanhf(s0);
            float hv1 = tanhf(s1);
            hs[((size_t)(b0 + eb0) * T_ + t) * NH_ + j0g + ej] = hv0;
            hs[((size_t)(b0 + eb1) * T_ + t) * NH_ + j0g + ej] = hv1;
        }

        // ---- publish progress: fence, join, release flag ----
        __threadfence();
        __syncthreads();
        if (tid == 0) st_rel(&g_flag[bt][jt], (unsigned)(t + 1));
    }
}

// ---------------------------------------------------------------------------
// Launch: [sgemm(pre), rnn_seq4, sgemm(y)]
// ---------------------------------------------------------------------------
extern "C" void kernel_launch(void* const* d_in, const int* in_sizes, int n_in,
                              void* d_out, int out_size)
{
    const float* x  = (const float*)d_in[0];
    const float* h0 = (const float*)d_in[1];
    const float* Wi = (const float*)d_in[2];
    const float* Wh = (const float*)d_in[3];
    const float* Wy = (const float*)d_in[4];

    float* y  = (float*)d_out;
    float* hs = y + (size_t)B_ * T_ * NY_;

    // Phase 1: pre = x @ Wi^T -> hs region (scratch)
    {
        dim3 grid(NH_ / 64, (B_ * T_) / 128);
        sgemm_nt<128, 64, 16, 8, 4, 256><<<grid, 256>>>(x, Wi, hs, B_ * T_, NX_ == NX_ ? NH_ : NH_, NX_);
    }
    // Phase 2: sequential recurrence
    {
        cudaFuncSetAttribute(rnn_seq4,
                             cudaFuncAttributeMaxDynamicSharedMemorySize, SMEM_BYTES);
        rnn_seq4<<<128, NTHR, SMEM_BYTES>>>(Wh, h0, hs);
    }
    // Phase 3: y = hs @ Wy^T
    {
        dim3 grid(NY_ / 64, (B_ * T_) / 128);
        sgemm_nt<128, 64, 16, 8, 4, 256><<<grid, 256>>>(hs, Wy, y, B_ * T_, NY_, NH_);
    }
}

// round 10
// speedup vs baseline: 1.1883x; 1.1883x over previous
#include <cuda_runtime.h>
#include <math.h>
#include <stdint.h>

#define B_  128
#define T_  1024
#define NX_ 256
#define NH_ 512
#define NY_ 256

// Progress flags: g_flag2[bt][group][jt], row padded to 32 words (128B).
__device__ unsigned g_flag2[16][2][32];

// ---------------------------------------------------------------------------
// Generic NT SGEMM (proven): C[m][n] = sum_k A[m][k] * B[n][k]
// ---------------------------------------------------------------------------
template <int BM, int BN, int BK, int TM, int TN, int NT>
__global__ __launch_bounds__(NT) void sgemm_nt(
    const float* __restrict__ A,
    const float* __restrict__ Bm,
    float* __restrict__ C,
    int M, int N, int K)
{
    __shared__ float As[BK][BM];
    __shared__ float Bs[BK][BN];

    const int tid = threadIdx.x;
    const int m0 = blockIdx.y * BM;
    const int n0 = blockIdx.x * BN;
    const int tx = tid % (BN / TN);
    const int ty = tid / (BN / TN);

    float acc[TM][TN];
#pragma unroll
    for (int i = 0; i < TM; i++)
#pragma unroll
        for (int j = 0; j < TN; j++) acc[i][j] = 0.0f;

    for (int k0 = 0; k0 < K; k0 += BK) {
#pragma unroll
        for (int i = tid; i < BM * (BK / 4); i += NT) {
            int m = i / (BK / 4);
            int kq = (i % (BK / 4)) * 4;
            float4 v = *(const float4*)(A + (long)(m0 + m) * K + k0 + kq);
            As[kq + 0][m] = v.x;
            As[kq + 1][m] = v.y;
            As[kq + 2][m] = v.z;
            As[kq + 3][m] = v.w;
        }
#pragma unroll
        for (int i = tid; i < BN * (BK / 4); i += NT) {
            int n = i / (BK / 4);
            int kq = (i % (BK / 4)) * 4;
            float4 v = *(const float4*)(Bm + (long)(n0 + n) * K + k0 + kq);
            Bs[kq + 0][n] = v.x;
            Bs[kq + 1][n] = v.y;
            Bs[kq + 2][n] = v.z;
            Bs[kq + 3][n] = v.w;
        }
        __syncthreads();

#pragma unroll
        for (int k = 0; k < BK; ++k) {
            float a[TM], b[TN];
#pragma unroll
            for (int i = 0; i < TM; i++) a[i] = As[k][ty * TM + i];
#pragma unroll
            for (int j = 0; j < TN; j++) b[j] = Bs[k][tx * TN + j];
#pragma unroll
            for (int i = 0; i < TM; i++)
#pragma unroll
                for (int j = 0; j < TN; j++) acc[i][j] = fmaf(a[i], b[j], acc[i][j]);
        }
        __syncthreads();
    }

#pragma unroll
    for (int i = 0; i < TM; i++) {
        float4 v = make_float4(acc[i][0], acc[i][1], acc[i][2], acc[i][3]);
        *(float4*)(C + (long)(m0 + ty * TM + i) * N + n0 + tx * TN) = v;
    }
}

// ---------------------------------------------------------------------------
// Helpers
// ---------------------------------------------------------------------------
__device__ __forceinline__ void ffma2(unsigned long long& d,
                                      unsigned long long a, unsigned long long b)
{
    asm("fma.rn.f32x2 %0, %1, %2, %0;" : "+l"(d) : "l"(a), "l"(b));
}
__device__ __forceinline__ void unpack2(unsigned long long v, float& lo, float& hi)
{
    asm("mov.b64 {%0, %1}, %2;" : "=f"(lo), "=f"(hi) : "l"(v));
}
__device__ __forceinline__ unsigned ld_acq(const unsigned* p)
{
    unsigned v;
    asm volatile("ld.global.acquire.gpu.u32 %0, [%1];" : "=r"(v) : "l"(p) : "memory");
    return v;
}
__device__ __forceinline__ void st_rel(unsigned* p, unsigned v)
{
    asm volatile("st.global.release.gpu.u32 [%0], %1;" :: "l"(p), "r"(v) : "memory");
}

// ---------------------------------------------------------------------------
// Sequential recurrence v5: two phase-shifted batch groups per CTA.
//
// Grid = 128 CTAs = 16 bt x 8 jt. 256 threads = 8 warps (k-split 64 each).
// CTA owns 8 batches (groups A=b0..3, B=b4..7) x 64 output columns.
// Per warp, per step: waitA, computeA, publishA, waitB, computeB, publishB —
// group X's flag/h L2 propagation hides under group Y's compute.
// W (2 cols x 64 k) register-resident; h round-trips through hs.
// SMEM: hTw[8w][2g][4b][68] 17.4KB + red[2g][8w][4b][64j] u64 32KB.
// ---------------------------------------------------------------------------
#define NTHR     256
#define HTW_STR  272                       // 4*68 floats per (warp,group)
#define RED_FOFF (16 * HTW_STR)            // 4352 floats
#define SMEM_BYTES (RED_FOFF * 4 + 2 * 2048 * 8)   // 17408 + 32768 = 50176

struct GroupCtx {
    unsigned* flags;          // 8 peer flags for this (bt, group)
    float* hTw;               // warp-private [4][68]
    unsigned long long* red;  // [8][4][64]
    int b0g;                  // first global batch of the group
};

__device__ __forceinline__ void rnn_do_group(
    int t, const GroupCtx& G,
    const float* __restrict__ h0, float* __restrict__ hs,
    const unsigned long long* W, float pre,
    int jt, int j0g, int kw0, int tid, int lane, int wid, int eb, int ej)
{
    // ---- wait: all 8 peer CTAs published this group's h_{t-1} ----
    if (t > 0) {
        for (;;) {
            unsigned v = (lane < 8) ? ld_acq(G.flags + lane) : (unsigned)t;
            if (__all_sync(0xffffffffu, (v - (unsigned)t) <= 1u)) break;
            __nanosleep(20);
        }
    }

    // ---- warp-local reload: 4 batches x 64-k slice -> hTw ----
    {
        int rb = lane >> 3;                 // 0..3
        int f4 = (lane & 7) * 8;            // float offset, 2 float4 per lane
        const float* src = (t == 0)
            ? h0 + (size_t)(G.b0g + rb) * NH_ + kw0 + f4
            : hs + ((size_t)(G.b0g + rb) * T_ + (t - 1)) * NH_ + kw0 + f4;
        float4 v0 = __ldcg((const float4*)(src));
        float4 v1 = __ldcg((const float4*)(src + 4));
        *(float4*)&G.hTw[rb * 68 + f4]     = v0;
        *(float4*)&G.hTw[rb * 68 + f4 + 4] = v1;
    }
    __syncwarp();

    // ---- k-loop: 4 FFMA2 per broadcast LDS.128 ----
    unsigned long long acc[4][2];
#pragma unroll
    for (int b = 0; b < 4; ++b) { acc[b][0] = 0ull; acc[b][1] = 0ull; }

#pragma unroll
    for (int b = 0; b < 4; ++b) {
        const float* hb = &G.hTw[b * 68];
#pragma unroll
        for (int q = 0; q < 16; ++q) {
            ulonglong2 va = *(const ulonglong2*)(hb + q * 4);   // broadcast
            ffma2(acc[b][0], va.x, W[2 * q]);
            ffma2(acc[b][0], va.y, W[2 * q + 1]);
            ffma2(acc[b][1], va.x, W[32 + 2 * q]);
            ffma2(acc[b][1], va.y, W[32 + 2 * q + 1]);
        }
    }

    // ---- stash partials: red[wid][b][lane*2 + c] (STS.128) ----
#pragma unroll
    for (int b = 0; b < 4; ++b) {
        ulonglong2 v; v.x = acc[b][0]; v.y = acc[b][1];
        *(ulonglong2*)&G.red[(size_t)wid * 256 + b * 64 + lane * 2] = v;
    }
    __syncthreads();

    // ---- reduce 8 warps, fold k-pairs, add pre, tanh, publish h ----
    {
        float s = pre;
#pragma unroll
        for (int w = 0; w < 8; ++w) {
            float lo, hi;
            unpack2(G.red[(size_t)w * 256 + eb * 64 + ej], lo, hi);
            s += lo + hi;
        }
        float hv = tanhf(s);
        hs[((size_t)(G.b0g + eb) * T_ + t) * NH_ + j0g + ej] = hv;
    }

    // ---- fence, join, release group flag ----
    __threadfence();
    __syncthreads();
    if (tid == 0) st_rel(G.flags + jt, (unsigned)(t + 1));
}

__global__ __launch_bounds__(NTHR, 1) void rnn_seq5(
    const float* __restrict__ Wh,   // [NH][NH]
    const float* __restrict__ h0,   // [B][NH]
    float* __restrict__ hs)         // [B][T][NH]: pre in, h out (in place)
{
    extern __shared__ float sm[];

    const int tid  = threadIdx.x;
    const int wid  = tid >> 5;
    const int lane = tid & 31;

    const int jt  = blockIdx.x & 7;
    const int bt  = blockIdx.x >> 3;
    const int j0g = jt * 64;
    const int b0  = bt * 8;
    const int kw0 = wid * 64;

    // ---- Wh slice into registers (cols lane*2, lane*2+1; k = kw0..+64) ----
    unsigned long long W[64];
#pragma unroll
    for (int c = 0; c < 2; ++c) {
        const float* row = Wh + (size_t)(j0g + lane * 2 + c) * NH_ + kw0;
#pragma unroll
        for (int q = 0; q < 16; ++q) {
            ulonglong2 v = *(const ulonglong2*)(row + q * 4);
            W[c * 32 + 2 * q]     = v.x;
            W[c * 32 + 2 * q + 1] = v.y;
        }
    }

    // epilogue mapping: one output per thread per group
    const int eb = tid >> 6;   // 0..3
    const int ej = tid & 63;

    GroupCtx GA, GB;
    GA.flags = &g_flag2[bt][0][0];
    GB.flags = &g_flag2[bt][1][0];
    GA.hTw   = sm + (wid * 2 + 0) * HTW_STR;
    GB.hTw   = sm + (wid * 2 + 1) * HTW_STR;
    GA.red   = (unsigned long long*)(sm + RED_FOFF);
    GB.red   = GA.red + 2048;
    GA.b0g   = b0;
    GB.b0g   = b0 + 4;

    for (int t = 0; t < T_; ++t) {
        // prefetch both groups' pre-activations (overlaps waitA)
        float preA = __ldcg(hs + ((size_t)(b0 + eb) * T_ + t) * NH_ + j0g + ej);
        float preB = __ldcg(hs + ((size_t)(b0 + 4 + eb) * T_ + t) * NH_ + j0g + ej);

        rnn_do_group(t, GA, h0, hs, W, preA, jt, j0g, kw0, tid, lane, wid, eb, ej);
        rnn_do_group(t, GB, h0, hs, W, preB, jt, j0g, kw0, tid, lane, wid, eb, ej);
    }
}

// ---------------------------------------------------------------------------
// Launch: [sgemm(pre), rnn_seq5, sgemm(y)]
// ---------------------------------------------------------------------------
extern "C" void kernel_launch(void* const* d_in, const int* in_sizes, int n_in,
                              void* d_out, int out_size)
{
    const float* x  = (const float*)d_in[0];
    const float* h0 = (const float*)d_in[1];
    const float* Wi = (const float*)d_in[2];
    const float* Wh = (const float*)d_in[3];
    const float* Wy = (const float*)d_in[4];

    float* y  = (float*)d_out;
    float* hs = y + (size_t)B_ * T_ * NY_;

    // Phase 1: pre = x @ Wi^T -> hs region (scratch)
    {
        dim3 grid(NH_ / 64, (B_ * T_) / 128);
        sgemm_nt<128, 64, 16, 8, 4, 256><<<grid, 256>>>(x, Wi, hs, B_ * T_, NH_, NX_);
    }
    // Phase 2: sequential recurrence (phase-shifted group interleave)
    {
        cudaFuncSetAttribute(rnn_seq5,
                             cudaFuncAttributeMaxDynamicSharedMemorySize, SMEM_BYTES);
        rnn_seq5<<<128, NTHR, SMEM_BYTES>>>(Wh, h0, hs);
    }
    // Phase 3: y = hs @ Wy^T
    {
        dim3 grid(NY_ / 64, (B_ * T_) / 128);
        sgemm_nt<128, 64, 16, 8, 4, 256><<<grid, 256>>>(hs, Wy, y, B_ * T_, NY_, NH_);
    }
}